// round 14
// baseline (speedup 1.0000x reference)
#include <cuda_runtime.h>
#include <cuda_bf16.h>
#include <math.h>

// ---------------- problem constants ----------------
#define BB    64
#define TT    1024
#define IDIM  120
#define HDIM  320
#define H4    1280
#define KCLS  72
#define LMAXC 96
#define SSTATES 193          // 2*LMAX+1
#define NEGV  (-1e30f)
#define MROWS (BB*TT)        // 65536
#define GXH   ((size_t)MROWS * H4)   // per-dir gx stride (elements)

// ---------------- static device scratch ----------------
__device__ float g_gx[2ull * MROWS * H4];     // 671 MB: input-proj gates, both dirs
__device__ float g_xA[(size_t)MROWS * 640];   // 168 MB
__device__ float g_xB[(size_t)MROWS * 640];   // 168 MB
__device__ float g_z [(size_t)MROWS * KCLS];  // 18.9 MB (logits -> normalized logp, in place)
__device__ float g_h [2 * 2 * HDIM * BB];     // ping-pong h [phase][dir][u][b]
__device__ float g_dt[MROWS];                 // per (b,t) den terms
__device__ float g_den[BB];
__device__ float g_num[BB];
__device__ unsigned g_bar;

// =======================================================
// SGEMM: C[m][n] = sum_k A[m][k] * W[n][k] + bias[n]
// A row-major [M x Kd], W row-major [N x Kd].
// BM=BN=128, BK=8, 256 threads, 8x8 per thread.
// Requires: M % 128 == 0, Kd % 8 == 0, Kd % 4 == 0 (float4 loads).
// N handled with predicates (for N=72).
// =======================================================
__global__ __launch_bounds__(256, 2)
void sgemm_bias(const float* __restrict__ A, const float* __restrict__ W,
                const float* __restrict__ bias, float* __restrict__ C,
                int M, int N, int Kd)
{
    __shared__ float As[8][128];
    __shared__ float Bs[8][128];

    const int tid = threadIdx.x;
    const int tx = tid & 15;        // 0..15 -> n
    const int ty = tid >> 4;        // 0..15 -> m
    const int bm = blockIdx.y;
    const int bn = blockIdx.x;

    const int lr  = tid >> 1;       // 0..127
    const int lc  = (tid & 1) << 2; // 0 or 4

    const float* Ab = A + ((size_t)(bm * 128 + lr)) * Kd + lc;
    const int wn = bn * 128 + lr;
    const float* Wb = W + (size_t)wn * Kd + lc;
    const bool wok = (wn < N);

    float acc[8][8];
#pragma unroll
    for (int i = 0; i < 8; i++)
#pragma unroll
        for (int j = 0; j < 8; j++) acc[i][j] = 0.f;

    const int nk = Kd >> 3;
    for (int kt = 0; kt < nk; ++kt) {
        const int k0 = kt << 3;
        float4 av = *(const float4*)(Ab + k0);
        float4 wv = make_float4(0.f, 0.f, 0.f, 0.f);
        if (wok) wv = *(const float4*)(Wb + k0);

        As[lc + 0][lr] = av.x; As[lc + 1][lr] = av.y;
        As[lc + 2][lr] = av.z; As[lc + 3][lr] = av.w;
        Bs[lc + 0][lr] = wv.x; Bs[lc + 1][lr] = wv.y;
        Bs[lc + 2][lr] = wv.z; Bs[lc + 3][lr] = wv.w;
        __syncthreads();

#pragma unroll
        for (int k = 0; k < 8; ++k) {
            float ar[8], br[8];
            *(float4*)(ar)     = *(const float4*)(&As[k][ty * 8]);
            *(float4*)(ar + 4) = *(const float4*)(&As[k][ty * 8 + 4]);
            *(float4*)(br)     = *(const float4*)(&Bs[k][tx * 8]);
            *(float4*)(br + 4) = *(const float4*)(&Bs[k][tx * 8 + 4]);
#pragma unroll
            for (int i = 0; i < 8; i++)
#pragma unroll
                for (int j = 0; j < 8; j++)
                    acc[i][j] += ar[i] * br[j];
        }
        __syncthreads();
    }

    // epilogue
#pragma unroll
    for (int i = 0; i < 8; i++) {
        const size_t m = (size_t)(bm * 128 + ty * 8 + i);
        float* crow = C + m * (size_t)N;
#pragma unroll
        for (int j = 0; j < 8; j++) {
            const int n = bn * 128 + tx * 8 + j;
            if (n < N) crow[n] = acc[i][j] + __ldg(bias + n);
        }
    }
}

// =======================================================
// Grid barrier helpers (persistent recurrence kernel)
// =======================================================
__device__ __forceinline__ void gridbar(unsigned target)
{
    __threadfence();          // release this thread's global writes
    __syncthreads();
    if (threadIdx.x == 0) {
        atomicAdd(&g_bar, 1u);
        unsigned v;
        do {
            asm volatile("ld.acquire.gpu.global.u32 %0, [%1];"
                         : "=r"(v) : "l"(&g_bar) : "memory");
        } while (v < target);
    }
    __syncthreads();
}

__global__ void reset_kernel() { if (threadIdx.x == 0) g_bar = 0u; }

// =======================================================
// Persistent BLSTM recurrence, one layer, both directions.
// grid = 128 CTAs x 320 threads. CTA: dir = blk>>6, cid = blk&63.
// CTA owns units u in [cid*5, cid*5+5) for all 64 batches.
// thread: u_local = tid>>6 (0..4), b = tid&63.
// gx layout: [dir][(b*1024+t)][1280]   (plain GEMM output)
// xout     : [(b*1024+t)][640], dir half at dir*320
// =======================================================
__global__ void recur_kernel(const float* __restrict__ gx,
                             const float* __restrict__ Whh,   // [2][1280][320]
                             const int*   __restrict__ lens,
                             float* __restrict__ xout)
{
    extern __shared__ float smem[];
    float* ws = smem;            // [5][320][4] gate-interleaved = 6400 floats
    float* hs = smem + 6400;     // [320 j][64 b] = 20480 floats

    const int tid = threadIdx.x;
    const int dir = blockIdx.x >> 6;
    const int cid = blockIdx.x & 63;
    const int u_local = tid >> 6;
    const int b = tid & 63;
    const int u = cid * 5 + u_local;
    const int len = __ldg(lens + b);

    // load Whh rows (i,f,g,o for each owned unit), interleaved as float4 per j
    {
        const float* Wd = Whh + (size_t)dir * H4 * HDIM;
        for (int i = tid; i < 6400; i += 320) {
            const int g  = i & 3;
            const int r  = i >> 2;      // ul*320 + j
            const int j  = r % 320;
            const int ul = r / 320;
            ws[i] = __ldg(Wd + (size_t)(g * HDIM + cid * 5 + ul) * HDIM + j);
        }
    }

    // h0 = 0
    g_h[((size_t)(0 * 2 + dir) * HDIM + u) * BB + b] = 0.f;
    float c = 0.f;
    unsigned bar = 0;
    gridbar(++bar * gridDim.x);

    const float* gxd = gx + (size_t)dir * GXH;

    for (int s = 0; s < TT; ++s) {
        const int p = s & 1;
        // stage h_prev (whole dir slab, 20480 floats) into smem; must bypass L1
        {
            const float4* src = (const float4*)(g_h + (size_t)(p * 2 + dir) * HDIM * BB);
            float4* dst = (float4*)hs;
#pragma unroll
            for (int k = 0; k < 16; ++k)
                dst[k * 320 + tid] = __ldcg(src + k * 320 + tid);
        }
        __syncthreads();

        const int t = dir ? ((s < len) ? (len - 1 - s) : s) : s;
        const float* gr = gxd + ((size_t)b * TT + t) * H4 + u;
        float ai = __ldg(gr);
        float af = __ldg(gr + 320);
        float ag = __ldg(gr + 640);
        float ao = __ldg(gr + 960);

        const float* wbase = ws + u_local * 1280;
#pragma unroll 8
        for (int j = 0; j < 320; ++j) {
            const float h = hs[j * 64 + b];
            const float4 w = *(const float4*)(wbase + j * 4);
            ai += w.x * h;
            af += w.y * h;
            ag += w.z * h;
            ao += w.w * h;
        }

        const float fi = 1.f / (1.f + expf(-ai));
        const float ff = 1.f / (1.f + expf(-af));
        const float fo = 1.f / (1.f + expf(-ao));
        c = ff * c + fi * tanhf(ag);
        const float h = fo * tanhf(c);

        g_h[((size_t)((p ^ 1) * 2 + dir) * HDIM + u) * BB + b] = h;
        xout[((size_t)b * TT + t) * 640 + dir * HDIM + u] = h;

        gridbar(++bar * gridDim.x);
    }
}

// =======================================================
// log_softmax over 72 classes (warp per row) + den term per (b,t)
// =======================================================
__global__ void lsm_kernel(float* __restrict__ z, const int* __restrict__ lens)
{
    const int row = blockIdx.x * 8 + (threadIdx.x >> 5);
    const int lane = threadIdx.x & 31;
    if (row >= MROWS) return;
    float* zr = z + (size_t)row * KCLS;

    float v0 = zr[lane];
    float v1 = zr[lane + 32];
    float v2 = (lane < 8) ? zr[lane + 64] : -3.4e38f;

    float m = fmaxf(fmaxf(v0, v1), v2);
#pragma unroll
    for (int o = 16; o; o >>= 1) m = fmaxf(m, __shfl_xor_sync(0xffffffffu, m, o));
    float s = expf(v0 - m) + expf(v1 - m) + ((lane < 8) ? expf(v2 - m) : 0.f);
#pragma unroll
    for (int o = 16; o; o >>= 1) s += __shfl_xor_sync(0xffffffffu, s, o);
    const float lse = m + logf(s);

    v0 -= lse; v1 -= lse;
    zr[lane] = v0; zr[lane + 32] = v1;
    if (lane < 8) { v2 -= lse; zr[lane + 64] = v2; } else v2 = -3.4e38f;

    // den term: logsumexp of the normalized row (second honest pass)
    float m2 = fmaxf(fmaxf(v0, v1), v2);
#pragma unroll
    for (int o = 16; o; o >>= 1) m2 = fmaxf(m2, __shfl_xor_sync(0xffffffffu, m2, o));
    float s2 = expf(v0 - m2) + expf(v1 - m2) + ((lane < 8) ? expf(v2 - m2) : 0.f);
#pragma unroll
    for (int o = 16; o; o >>= 1) s2 += __shfl_xor_sync(0xffffffffu, s2, o);

    if (lane == 0) {
        const int b = row >> 10, t = row & 1023;
        g_dt[row] = (t < __ldg(lens + b)) ? (m2 + logf(s2)) : 0.f;
    }
}

__global__ void den_reduce()
{
    const int b = blockIdx.x;
    __shared__ float sm[256];
    float s = 0.f;
    for (int t = threadIdx.x; t < TT; t += 256) s += g_dt[b * TT + t];
    sm[threadIdx.x] = s;
    __syncthreads();
    for (int o = 128; o; o >>= 1) {
        if (threadIdx.x < o) sm[threadIdx.x] += sm[threadIdx.x + o];
        __syncthreads();
    }
    if (threadIdx.x == 0) g_den[b] = sm[0];
}

// =======================================================
// CTC forward (alpha recursion), one CTA per batch, 256 threads.
// =======================================================
__global__ void ctc_kernel(const float* __restrict__ z,
                           const int* __restrict__ labels,
                           const int* __restrict__ ilen,
                           const int* __restrict__ llen)
{
    const int b = blockIdx.x;
    const int s = threadIdx.x;
    __shared__ float A0[SSTATES];
    __shared__ float A1[SSTATES];

    const int Ll = __ldg(llen + b);
    const int Tl = __ldg(ilen + b);
    const float* zb = z + (size_t)b * TT * KCLS;

    int lab = 0;
    bool can_skip = false;
    bool valid = false;
    if (s < SSTATES) {
        if (s & 1) {
            lab = __ldg(labels + b * LMAXC + (s >> 1));
            can_skip = (s < 3) ? true
                     : (lab != __ldg(labels + b * LMAXC + ((s - 2) >> 1)));
        }
        valid = s < (2 * Ll + 1);
    }

    if (s < SSTATES) {
        float a;
        if (s == 0)      a = zb[0];
        else if (s == 1) a = zb[lab];
        else             a = NEGV;
        if (!valid) a = NEGV;
        A0[s] = a;
    }
    __syncthreads();

    float* cur = A0;
    float* nxt = A1;
    for (int t = 1; t < Tl; ++t) {
        if (s < SSTATES) {
            const float a1 = cur[s];
            const float a2 = (s >= 1) ? cur[s - 1] : NEGV;
            const float a3 = (s >= 2 && can_skip) ? cur[s - 2] : NEGV;
            const float m = fmaxf(a1, fmaxf(a2, a3));
            float v = m + logf(expf(a1 - m) + expf(a2 - m) + expf(a3 - m));
            v += zb[(size_t)t * KCLS + lab];
            if (!valid) v = NEGV;
            nxt[s] = v;
        }
        __syncthreads();
        float* tmp = cur; cur = nxt; nxt = tmp;
    }

    if (s == 0) {
        const int L2 = 2 * Ll;
        const float a = cur[L2];
        const float bq = cur[L2 - 1];
        const float m = fmaxf(a, bq);
        g_num[b] = m + logf(expf(a - m) + expf(bq - m));
    }
}

__global__ void finalize_kernel(float* __restrict__ out)
{
    __shared__ float sm[64];
    const int b = threadIdx.x;
    sm[b] = g_den[b] - 1.1f * g_num[b];
    __syncthreads();
    for (int o = 32; o; o >>= 1) {
        if (b < o) sm[b] += sm[b + o];
        __syncthreads();
    }
    if (b == 0) out[0] = sm[0] / 64.f;
}

// =======================================================
// host launcher
// =======================================================
extern "C" void kernel_launch(void* const* d_in, const int* in_sizes, int n_in,
                              void* d_out, int out_size)
{
    const float* logits = (const float*)d_in[0];
    const int*   labels = (const int*)d_in[1];
    const int*   ilen   = (const int*)d_in[2];
    const int*   llen   = (const int*)d_in[3];
    const float* Wih0   = (const float*)d_in[4];   // [2][1280][120]
    const float* Whh0   = (const float*)d_in[5];   // [2][1280][320]
    const float* b0     = (const float*)d_in[6];   // [2][1280]
    const float* Wih    = (const float*)d_in[7];   // [2][2][1280][640]
    const float* Whh    = (const float*)d_in[8];   // [2][2][1280][320]
    const float* bbias  = (const float*)d_in[9];   // [2][2][1280]
    const float* Wlin   = (const float*)d_in[10];  // [72][640]
    const float* blin   = (const float*)d_in[11];  // [72]

    float *gx, *xA, *xB, *z;
    cudaGetSymbolAddress((void**)&gx, g_gx);
    cudaGetSymbolAddress((void**)&xA, g_xA);
    cudaGetSymbolAddress((void**)&xB, g_xB);
    cudaGetSymbolAddress((void**)&z,  g_z);

    const int SMEM_REC = (6400 + 20480) * 4;   // 107,520 B
    cudaFuncSetAttribute(recur_kernel, cudaFuncAttributeMaxDynamicSharedMemorySize, SMEM_REC);

    dim3 g10(10, 512), g1(1, 512);

    // ---- layer 0 (Kd = 120) ----
    sgemm_bias<<<g10, 256>>>(logits, Wih0,                     b0,        gx,       MROWS, H4, IDIM);
    sgemm_bias<<<g10, 256>>>(logits, Wih0 + (size_t)H4 * IDIM, b0 + H4,   gx + GXH, MROWS, H4, IDIM);
    reset_kernel<<<1, 32>>>();
    recur_kernel<<<128, 320, SMEM_REC>>>(gx, Whh0, ilen, xA);

    // ---- layer 1 (Kd = 640) ----
    sgemm_bias<<<g10, 256>>>(xA, Wih,                         bbias,          gx,       MROWS, H4, 640);
    sgemm_bias<<<g10, 256>>>(xA, Wih + (size_t)1 * H4 * 640,  bbias + H4,     gx + GXH, MROWS, H4, 640);
    reset_kernel<<<1, 32>>>();
    recur_kernel<<<128, 320, SMEM_REC>>>(gx, Whh, ilen, xB);

    // ---- layer 2 (Kd = 640) ----
    sgemm_bias<<<g10, 256>>>(xB, Wih + (size_t)2 * H4 * 640,  bbias + 2 * H4, gx,       MROWS, H4, 640);
    sgemm_bias<<<g10, 256>>>(xB, Wih + (size_t)3 * H4 * 640,  bbias + 3 * H4, gx + GXH, MROWS, H4, 640);
    reset_kernel<<<1, 32>>>();
    recur_kernel<<<128, 320, SMEM_REC>>>(gx, Whh + (size_t)2 * H4 * HDIM, ilen, xA);

    // ---- output projection + log_softmax + den ----
    sgemm_bias<<<g1, 256>>>(xA, Wlin, blin, z, MROWS, KCLS, 640);
    lsm_kernel<<<MROWS / 8, 256>>>(z, ilen);
    den_reduce<<<BB, 256>>>();

    // ---- CTC numerator + finalize ----
    ctc_kernel<<<BB, 256>>>(z, labels, ilen, llen);
    finalize_kernel<<<1, 64>>>((float*)d_out);
}

// round 16
// speedup vs baseline: 1.1982x; 1.1982x over previous
#include <cuda_runtime.h>
#include <cuda_bf16.h>
#include <math.h>
#include <stdint.h>

// ---------------- problem constants ----------------
#define BB    64
#define TT    1024
#define IDIM  120
#define HDIM  320
#define H4    1280
#define KCLS  72
#define LMAXC 96
#define SSTATES 193          // 2*LMAX+1
#define NEGV  (-1e30f)
#define MROWS (BB*TT)        // 65536
#define GXH   ((size_t)MROWS * H4)   // per-dir gx stride (elements)

// ---------------- static device scratch ----------------
__device__ float g_gx[2ull * MROWS * H4];     // input-proj gates, both dirs
__device__ float g_xA[(size_t)MROWS * 640];
__device__ float g_xB[(size_t)MROWS * 640];
__device__ float g_z [(size_t)MROWS * KCLS];
__device__ float g_h [2 * 2 * HDIM * BB];     // ping-pong h [phase][dir][u][b]
__device__ float g_dt[MROWS];
__device__ float g_den[BB];
__device__ float g_num[BB];
__device__ unsigned g_bar;

// =======================================================
// TF32 tensor-core GEMM: C[m][n] = sum_k A[m][k]*W[n][k] + bias[n]
// A [M x Kd] row-major, W [N x Kd] row-major.
// CTA tile 128x128, BK=16, 256 threads (8 warps, each 32x64),
// mma.sync.m16n8k8.tf32, double-buffered cp.async.
// Requires M%128==0, N%128==0, Kd%4==0.
// =======================================================
#define ASTR 20   // padded smem stride (floats) -> conflict-free frag LDS

__device__ __forceinline__ void cp_async16(unsigned int dst, const void* src, int src_bytes)
{
    asm volatile("cp.async.cg.shared.global [%0], [%1], 16, %2;\n"
                 :: "r"(dst), "l"(src), "r"(src_bytes));
}

__global__ __launch_bounds__(256)
void tf32_gemm(const float* __restrict__ A, const float* __restrict__ W,
               const float* __restrict__ bias, float* __restrict__ C,
               int M, int N, int Kd)
{
    __shared__ float As[2][128 * ASTR];
    __shared__ float Bs[2][128 * ASTR];

    const int tid  = threadIdx.x;
    const int lane = tid & 31;
    const int warp = tid >> 5;
    const int wm   = warp & 3;     // 0..3 -> 32-row slab
    const int wn   = warp >> 2;    // 0..1 -> 64-col slab
    const int gid  = lane >> 2;    // 0..7
    const int tig  = lane & 3;     // 0..3
    const int bm = blockIdx.y, bn = blockIdx.x;

    // loader mapping: thread handles one 16B chunk in each of 4 tile-halves
    const int lrow = tid >> 2;           // 0..63
    const int lcol = (tid & 3) << 2;     // 0,4,8,12

    const float* Arow0 = A + (size_t)(bm * 128 + lrow) * Kd;
    const float* Arow1 = A + (size_t)(bm * 128 + lrow + 64) * Kd;
    const float* Wrow0 = W + (size_t)(bn * 128 + lrow) * Kd;
    const float* Wrow1 = W + (size_t)(bn * 128 + lrow + 64) * Kd;

    const unsigned int sA = (unsigned int)__cvta_generic_to_shared(&As[0][0]);
    const unsigned int sB = (unsigned int)__cvta_generic_to_shared(&Bs[0][0]);
    const unsigned int dA0 = sA + (lrow * ASTR + lcol) * 4;
    const unsigned int dA1 = sA + ((lrow + 64) * ASTR + lcol) * 4;
    const unsigned int dB0 = sB + (lrow * ASTR + lcol) * 4;
    const unsigned int dB1 = sB + ((lrow + 64) * ASTR + lcol) * 4;
    const unsigned int bufB = 128 * ASTR * 4;   // bytes per buffer

    float acc[2][8][4];
#pragma unroll
    for (int i = 0; i < 2; i++)
#pragma unroll
        for (int j = 0; j < 8; j++)
#pragma unroll
            for (int q = 0; q < 4; q++) acc[i][j][q] = 0.f;

    const int nk = (Kd + 15) >> 4;

    // ---- issue loads for tile kt into buffer b ----
    auto issue = [&](int kt, int b) {
        const int k0 = kt << 4;
        const int kc = k0 + lcol;
        const int ok = (kc < Kd) ? 16 : 0;     // Kd%4==0 -> all-or-nothing 16B chunks
        const int off = ok ? kc : 0;
        const unsigned int bo = b ? bufB : 0u;
        cp_async16(dA0 + bo, Arow0 + off, ok);
        cp_async16(dA1 + bo, Arow1 + off, ok);
        cp_async16(dB0 + bo, Wrow0 + off, ok);
        cp_async16(dB1 + bo, Wrow1 + off, ok);
    };

    issue(0, 0);
    asm volatile("cp.async.commit_group;\n" ::: "memory");

    for (int kt = 0; kt < nk; ++kt) {
        const int cb = kt & 1;
        if (kt + 1 < nk) {
            issue(kt + 1, cb ^ 1);
            asm volatile("cp.async.commit_group;\n" ::: "memory");
            asm volatile("cp.async.wait_group 1;\n" ::: "memory");
        } else {
            asm volatile("cp.async.wait_group 0;\n" ::: "memory");
        }
        __syncthreads();

        const float* Ab = &As[cb][(wm * 32) * ASTR];
        const float* Bb = &Bs[cb][(wn * 64) * ASTR];

#pragma unroll
        for (int k8 = 0; k8 < 2; ++k8) {
            const int kc = k8 * 8;
            unsigned int af[2][4], bf[8][2];
#pragma unroll
            for (int mt = 0; mt < 2; ++mt) {
                const float* p = Ab + mt * 16 * ASTR + kc;
                af[mt][0] = __float_as_uint(p[gid * ASTR + tig]);
                af[mt][1] = __float_as_uint(p[(gid + 8) * ASTR + tig]);
                af[mt][2] = __float_as_uint(p[gid * ASTR + tig + 4]);
                af[mt][3] = __float_as_uint(p[(gid + 8) * ASTR + tig + 4]);
            }
#pragma unroll
            for (int nt = 0; nt < 8; ++nt) {
                const float* p = Bb + nt * 8 * ASTR + kc;
                bf[nt][0] = __float_as_uint(p[gid * ASTR + tig]);
                bf[nt][1] = __float_as_uint(p[gid * ASTR + tig + 4]);
            }
#pragma unroll
            for (int mt = 0; mt < 2; ++mt)
#pragma unroll
                for (int nt = 0; nt < 8; ++nt) {
                    asm volatile(
                        "mma.sync.aligned.m16n8k8.row.col.f32.tf32.tf32.f32 "
                        "{%0,%1,%2,%3}, {%4,%5,%6,%7}, {%8,%9}, {%0,%1,%2,%3};\n"
                        : "+f"(acc[mt][nt][0]), "+f"(acc[mt][nt][1]),
                          "+f"(acc[mt][nt][2]), "+f"(acc[mt][nt][3])
                        : "r"(af[mt][0]), "r"(af[mt][1]), "r"(af[mt][2]), "r"(af[mt][3]),
                          "r"(bf[nt][0]), "r"(bf[nt][1]));
                }
        }
        __syncthreads();
    }

    // ---- epilogue: bias + store (float2) ----
#pragma unroll
    for (int mt = 0; mt < 2; ++mt) {
        const int m0 = bm * 128 + wm * 32 + mt * 16 + gid;
#pragma unroll
        for (int nt = 0; nt < 8; ++nt) {
            const int n = bn * 128 + wn * 64 + nt * 8 + 2 * tig;
            const float b0 = __ldg(bias + n);
            const float b1 = __ldg(bias + n + 1);
            float2 v0 = make_float2(acc[mt][nt][0] + b0, acc[mt][nt][1] + b1);
            float2 v1 = make_float2(acc[mt][nt][2] + b0, acc[mt][nt][3] + b1);
            *(float2*)(C + (size_t)m0 * N + n) = v0;
            *(float2*)(C + (size_t)(m0 + 8) * N + n) = v1;
        }
    }
}

// =======================================================
// FFMA SGEMM (kept for the small N=72 projection)
// =======================================================
__global__ __launch_bounds__(256, 2)
void sgemm_bias(const float* __restrict__ A, const float* __restrict__ W,
                const float* __restrict__ bias, float* __restrict__ C,
                int M, int N, int Kd)
{
    __shared__ float Ass[8][128];
    __shared__ float Bss[8][128];

    const int tid = threadIdx.x;
    const int tx = tid & 15;
    const int ty = tid >> 4;
    const int bm = blockIdx.y;
    const int bn = blockIdx.x;

    const int lr  = tid >> 1;
    const int lc  = (tid & 1) << 2;

    const float* Ab = A + ((size_t)(bm * 128 + lr)) * Kd + lc;
    const int wn = bn * 128 + lr;
    const float* Wb = W + (size_t)wn * Kd + lc;
    const bool wok = (wn < N);

    float acc[8][8];
#pragma unroll
    for (int i = 0; i < 8; i++)
#pragma unroll
        for (int j = 0; j < 8; j++) acc[i][j] = 0.f;

    const int nk = Kd >> 3;
    for (int kt = 0; kt < nk; ++kt) {
        const int k0 = kt << 3;
        float4 av = *(const float4*)(Ab + k0);
        float4 wv = make_float4(0.f, 0.f, 0.f, 0.f);
        if (wok) wv = *(const float4*)(Wb + k0);

        Ass[lc + 0][lr] = av.x; Ass[lc + 1][lr] = av.y;
        Ass[lc + 2][lr] = av.z; Ass[lc + 3][lr] = av.w;
        Bss[lc + 0][lr] = wv.x; Bss[lc + 1][lr] = wv.y;
        Bss[lc + 2][lr] = wv.z; Bss[lc + 3][lr] = wv.w;
        __syncthreads();

#pragma unroll
        for (int k = 0; k < 8; ++k) {
            float ar[8], br[8];
            *(float4*)(ar)     = *(const float4*)(&Ass[k][ty * 8]);
            *(float4*)(ar + 4) = *(const float4*)(&Ass[k][ty * 8 + 4]);
            *(float4*)(br)     = *(const float4*)(&Bss[k][tx * 8]);
            *(float4*)(br + 4) = *(const float4*)(&Bss[k][tx * 8 + 4]);
#pragma unroll
            for (int i = 0; i < 8; i++)
#pragma unroll
                for (int j = 0; j < 8; j++)
                    acc[i][j] += ar[i] * br[j];
        }
        __syncthreads();
    }

#pragma unroll
    for (int i = 0; i < 8; i++) {
        const size_t m = (size_t)(bm * 128 + ty * 8 + i);
        float* crow = C + m * (size_t)N;
#pragma unroll
        for (int j = 0; j < 8; j++) {
            const int n = bn * 128 + tx * 8 + j;
            if (n < N) crow[n] = acc[i][j] + __ldg(bias + n);
        }
    }
}

// =======================================================
// Grid barrier (persistent recurrence kernel)
// =======================================================
__device__ __forceinline__ void gridbar(unsigned target)
{
    __threadfence();
    __syncthreads();
    if (threadIdx.x == 0) {
        atomicAdd(&g_bar, 1u);
        unsigned v;
        do {
            asm volatile("ld.acquire.gpu.global.u32 %0, [%1];"
                         : "=r"(v) : "l"(&g_bar) : "memory");
        } while (v < target);
    }
    __syncthreads();
}

__global__ void reset_kernel() { if (threadIdx.x == 0) g_bar = 0u; }

// =======================================================
// Persistent BLSTM recurrence, one layer, both directions.
// =======================================================
__global__ void recur_kernel(const float* __restrict__ gx,
                             const float* __restrict__ Whh,   // [2][1280][320]
                             const int*   __restrict__ lens,
                             float* __restrict__ xout)
{
    extern __shared__ float smem[];
    float* ws = smem;            // [5][320][4] gate-interleaved
    float* hs = smem + 6400;     // [320 j][64 b]

    const int tid = threadIdx.x;
    const int dir = blockIdx.x >> 6;
    const int cid = blockIdx.x & 63;
    const int u_local = tid >> 6;
    const int b = tid & 63;
    const int u = cid * 5 + u_local;
    const int len = __ldg(lens + b);

    {
        const float* Wd = Whh + (size_t)dir * H4 * HDIM;
        for (int i = tid; i < 6400; i += 320) {
            const int g  = i & 3;
            const int r  = i >> 2;
            const int j  = r % 320;
            const int ul = r / 320;
            ws[i] = __ldg(Wd + (size_t)(g * HDIM + cid * 5 + ul) * HDIM + j);
        }
    }

    g_h[((size_t)(0 * 2 + dir) * HDIM + u) * BB + b] = 0.f;
    float c = 0.f;
    unsigned bar = 0;
    gridbar(++bar * gridDim.x);

    const float* gxd = gx + (size_t)dir * GXH;

    for (int s = 0; s < TT; ++s) {
        const int p = s & 1;
        {
            const float4* src = (const float4*)(g_h + (size_t)(p * 2 + dir) * HDIM * BB);
            float4* dst = (float4*)hs;
#pragma unroll
            for (int k = 0; k < 16; ++k)
                dst[k * 320 + tid] = __ldcg(src + k * 320 + tid);
        }
        __syncthreads();

        const int t = dir ? ((s < len) ? (len - 1 - s) : s) : s;
        const float* gr = gxd + ((size_t)b * TT + t) * H4 + u;
        float ai = __ldg(gr);
        float af = __ldg(gr + 320);
        float ag = __ldg(gr + 640);
        float ao = __ldg(gr + 960);

        const float* wbase = ws + u_local * 1280;
#pragma unroll 8
        for (int j = 0; j < 320; ++j) {
            const float h = hs[j * 64 + b];
            const float4 w = *(const float4*)(wbase + j * 4);
            ai += w.x * h;
            af += w.y * h;
            ag += w.z * h;
            ao += w.w * h;
        }

        const float fi = 1.f / (1.f + expf(-ai));
        const float ff = 1.f / (1.f + expf(-af));
        const float fo = 1.f / (1.f + expf(-ao));
        c = ff * c + fi * tanhf(ag);
        const float h = fo * tanhf(c);

        g_h[((size_t)((p ^ 1) * 2 + dir) * HDIM + u) * BB + b] = h;
        xout[((size_t)b * TT + t) * 640 + dir * HDIM + u] = h;

        gridbar(++bar * gridDim.x);
    }
}

// =======================================================
// log_softmax over 72 classes (warp per row) + den term per (b,t)
// =======================================================
__global__ void lsm_kernel(float* __restrict__ z, const int* __restrict__ lens)
{
    const int row = blockIdx.x * 8 + (threadIdx.x >> 5);
    const int lane = threadIdx.x & 31;
    if (row >= MROWS) return;
    float* zr = z + (size_t)row * KCLS;

    float v0 = zr[lane];
    float v1 = zr[lane + 32];
    float v2 = (lane < 8) ? zr[lane + 64] : -3.4e38f;

    float m = fmaxf(fmaxf(v0, v1), v2);
#pragma unroll
    for (int o = 16; o; o >>= 1) m = fmaxf(m, __shfl_xor_sync(0xffffffffu, m, o));
    float s = expf(v0 - m) + expf(v1 - m) + ((lane < 8) ? expf(v2 - m) : 0.f);
#pragma unroll
    for (int o = 16; o; o >>= 1) s += __shfl_xor_sync(0xffffffffu, s, o);
    const float lse = m + logf(s);

    v0 -= lse; v1 -= lse;
    zr[lane] = v0; zr[lane + 32] = v1;
    if (lane < 8) { v2 -= lse; zr[lane + 64] = v2; } else v2 = -3.4e38f;

    float m2 = fmaxf(fmaxf(v0, v1), v2);
#pragma unroll
    for (int o = 16; o; o >>= 1) m2 = fmaxf(m2, __shfl_xor_sync(0xffffffffu, m2, o));
    float s2 = expf(v0 - m2) + expf(v1 - m2) + ((lane < 8) ? expf(v2 - m2) : 0.f);
#pragma unroll
    for (int o = 16; o; o >>= 1) s2 += __shfl_xor_sync(0xffffffffu, s2, o);

    if (lane == 0) {
        const int b = row >> 10, t = row & 1023;
        g_dt[row] = (t < __ldg(lens + b)) ? (m2 + logf(s2)) : 0.f;
    }
}

__global__ void den_reduce()
{
    const int b = blockIdx.x;
    __shared__ float sm[256];
    float s = 0.f;
    for (int t = threadIdx.x; t < TT; t += 256) s += g_dt[b * TT + t];
    sm[threadIdx.x] = s;
    __syncthreads();
    for (int o = 128; o; o >>= 1) {
        if (threadIdx.x < o) sm[threadIdx.x] += sm[threadIdx.x + o];
        __syncthreads();
    }
    if (threadIdx.x == 0) g_den[b] = sm[0];
}

// =======================================================
// CTC forward (alpha recursion), one CTA per batch
// =======================================================
__global__ void ctc_kernel(const float* __restrict__ z,
                           const int* __restrict__ labels,
                           const int* __restrict__ ilen,
                           const int* __restrict__ llen)
{
    const int b = blockIdx.x;
    const int s = threadIdx.x;
    __shared__ float A0[SSTATES];
    __shared__ float A1[SSTATES];

    const int Ll = __ldg(llen + b);
    const int Tl = __ldg(ilen + b);
    const float* zb = z + (size_t)b * TT * KCLS;

    int lab = 0;
    bool can_skip = false;
    bool valid = false;
    if (s < SSTATES) {
        if (s & 1) {
            lab = __ldg(labels + b * LMAXC + (s >> 1));
            can_skip = (s < 3) ? true
                     : (lab != __ldg(labels + b * LMAXC + ((s - 2) >> 1)));
        }
        valid = s < (2 * Ll + 1);
    }

    if (s < SSTATES) {
        float a;
        if (s == 0)      a = zb[0];
        else if (s == 1) a = zb[lab];
        else             a = NEGV;
        if (!valid) a = NEGV;
        A0[s] = a;
    }
    __syncthreads();

    float* cur = A0;
    float* nxt = A1;
    for (int t = 1; t < Tl; ++t) {
        if (s < SSTATES) {
            const float a1 = cur[s];
            const float a2 = (s >= 1) ? cur[s - 1] : NEGV;
            const float a3 = (s >= 2 && can_skip) ? cur[s - 2] : NEGV;
            const float m = fmaxf(a1, fmaxf(a2, a3));
            float v = m + logf(expf(a1 - m) + expf(a2 - m) + expf(a3 - m));
            v += zb[(size_t)t * KCLS + lab];
            if (!valid) v = NEGV;
            nxt[s] = v;
        }
        __syncthreads();
        float* tmp = cur; cur = nxt; nxt = tmp;
    }

    if (s == 0) {
        const int L2 = 2 * Ll;
        const float a = cur[L2];
        const float bq = cur[L2 - 1];
        const float m = fmaxf(a, bq);
        g_num[b] = m + logf(expf(a - m) + expf(bq - m));
    }
}

__global__ void finalize_kernel(float* __restrict__ out)
{
    __shared__ float sm[64];
    const int b = threadIdx.x;
    sm[b] = g_den[b] - 1.1f * g_num[b];
    __syncthreads();
    for (int o = 32; o; o >>= 1) {
        if (b < o) sm[b] += sm[b + o];
        __syncthreads();
    }
    if (b == 0) out[0] = sm[0] / 64.f;
}

// =======================================================
// host launcher
// =======================================================
extern "C" void kernel_launch(void* const* d_in, const int* in_sizes, int n_in,
                              void* d_out, int out_size)
{
    const float* logits = (const float*)d_in[0];
    const int*   labels = (const int*)d_in[1];
    const int*   ilen   = (const int*)d_in[2];
    const int*   llen   = (const int*)d_in[3];
    const float* Wih0   = (const float*)d_in[4];   // [2][1280][120]
    const float* Whh0   = (const float*)d_in[5];   // [2][1280][320]
    const float* b0     = (const float*)d_in[6];   // [2][1280]
    const float* Wih    = (const float*)d_in[7];   // [2][2][1280][640]
    const float* Whh    = (const float*)d_in[8];   // [2][2][1280][320]
    const float* bbias  = (const float*)d_in[9];   // [2][2][1280]
    const float* Wlin   = (const float*)d_in[10];  // [72][640]
    const float* blin   = (const float*)d_in[11];  // [72]

    float *gx, *xA, *xB, *z;
    cudaGetSymbolAddress((void**)&gx, g_gx);
    cudaGetSymbolAddress((void**)&xA, g_xA);
    cudaGetSymbolAddress((void**)&xB, g_xB);
    cudaGetSymbolAddress((void**)&z,  g_z);

    const int SMEM_REC = (6400 + 20480) * 4;   // 107,520 B
    cudaFuncSetAttribute(recur_kernel, cudaFuncAttributeMaxDynamicSharedMemorySize, SMEM_REC);

    dim3 g10(10, 512), g1(1, 512);

    // ---- layer 0 (Kd = 120) ----
    tf32_gemm<<<g10, 256>>>(logits, Wih0,                     b0,      gx,       MROWS, H4, IDIM);
    tf32_gemm<<<g10, 256>>>(logits, Wih0 + (size_t)H4 * IDIM, b0 + H4, gx + GXH, MROWS, H4, IDIM);
    reset_kernel<<<1, 32>>>();
    recur_kernel<<<128, 320, SMEM_REC>>>(gx, Whh0, ilen, xA);

    // ---- layer 1 (Kd = 640) ----
    tf32_gemm<<<g10, 256>>>(xA, Wih,                        bbias,      gx,       MROWS, H4, 640);
    tf32_gemm<<<g10, 256>>>(xA, Wih + (size_t)1 * H4 * 640, bbias + H4, gx + GXH, MROWS, H4, 640);
    reset_kernel<<<1, 32>>>();
    recur_kernel<<<128, 320, SMEM_REC>>>(gx, Whh, ilen, xB);

    // ---- layer 2 (Kd = 640) ----
    tf32_gemm<<<g10, 256>>>(xB, Wih + (size_t)2 * H4 * 640, bbias + 2 * H4, gx,       MROWS, H4, 640);
    tf32_gemm<<<g10, 256>>>(xB, Wih + (size_t)3 * H4 * 640, bbias + 3 * H4, gx + GXH, MROWS, H4, 640);
    reset_kernel<<<1, 32>>>();
    recur_kernel<<<128, 320, SMEM_REC>>>(gx, Whh + (size_t)2 * H4 * HDIM, ilen, xA);

    // ---- output projection + log_softmax + den ----
    sgemm_bias<<<g1, 256>>>(xA, Wlin, blin, z, MROWS, KCLS, 640);
    lsm_kernel<<<MROWS / 8, 256>>>(z, ilen);
    den_reduce<<<BB, 256>>>();

    // ---- CTC numerator + finalize ----
    ctc_kernel<<<BB, 256>>>(z, labels, ilen, llen);
    finalize_kernel<<<1, 64>>>((float*)d_out);
}